// round 1
// baseline (speedup 1.0000x reference)
#include <cuda_runtime.h>
#include <cuda_bf16.h>

// Problem: B=8, H=512, W=512
// Inputs (metadata order):
//   0: t        (8,1,1,1)    float32
//   1: I0       (8,512,512,3) float32
//   2: I1       (8,512,512,3) float32
//   3: interp   (8,512,512,5) float32
//   4: Fhat_t0  (8,512,512,2) float32
//   5: Fhat_t1  (8,512,512,2) float32
// Output: It (8,512,512,3) float32

#define W_DIM 512
#define H_DIM 512
#define B_DIM 8
#define HW (H_DIM * W_DIM)
#define NPIX (B_DIM * HW)

__device__ __forceinline__ float3 bilerp3(const float* __restrict__ img,
                                          float x, float y) {
    // img: one batch image (H,W,3)
    float x0f = floorf(x);
    float y0f = floorf(y);
    float wx = x - x0f;
    float wy = y - y0f;
    int x0 = min(max((int)x0f, 0), W_DIM - 1);
    int x1 = min(max((int)x0f + 1, 0), W_DIM - 1);
    int y0 = min(max((int)y0f, 0), H_DIM - 1);
    int y1 = min(max((int)y0f + 1, 0), H_DIM - 1);

    float wa = (1.f - wx) * (1.f - wy);  // (y0,x0)
    float wb = (1.f - wx) * wy;          // (y1,x0)
    float wc = wx * (1.f - wy);          // (y0,x1)
    float wd = wx * wy;                  // (y1,x1)

    const float* r0 = img + (size_t)y0 * (W_DIM * 3);
    const float* r1 = img + (size_t)y1 * (W_DIM * 3);
    int a = x0 * 3;
    int c = x1 * 3;

    float3 o;
    o.x = __ldg(r0 + a + 0) * wa + __ldg(r1 + a + 0) * wb
        + __ldg(r0 + c + 0) * wc + __ldg(r1 + c + 0) * wd;
    o.y = __ldg(r0 + a + 1) * wa + __ldg(r1 + a + 1) * wb
        + __ldg(r0 + c + 1) * wc + __ldg(r1 + c + 1) * wd;
    o.z = __ldg(r0 + a + 2) * wa + __ldg(r1 + a + 2) * wb
        + __ldg(r0 + c + 2) * wc + __ldg(r1 + c + 2) * wd;
    return o;
}

__global__ void __launch_bounds__(256)
imagecomp_kernel(const float* __restrict__ t,
                 const float* __restrict__ I0,
                 const float* __restrict__ I1,
                 const float* __restrict__ interp,
                 const float* __restrict__ F0,
                 const float* __restrict__ F1,
                 float* __restrict__ out) {
    int idx = blockIdx.x * blockDim.x + threadIdx.x;
    if (idx >= NPIX) return;

    int b = idx >> 18;          // / (512*512)
    int p = idx & (HW - 1);     // pixel within batch
    int yi = p >> 9;            // row
    int xi = p & (W_DIM - 1);   // col

    // interp: 5 floats per pixel (stride 20B; coalesced contiguous region)
    const float* ip = interp + (size_t)idx * 5;
    float c0 = __ldg(ip + 0);
    float c1 = __ldg(ip + 1);
    float c2 = __ldg(ip + 2);
    float c3 = __ldg(ip + 3);
    float c4 = __ldg(ip + 4);

    float2 f0 = __ldg((const float2*)F0 + idx);
    float2 f1 = __ldg((const float2*)F1 + idx);

    // Flows
    float ft0x = c0 + f0.x, ft0y = c1 + f0.y;
    float ft1x = c2 + f1.x, ft1y = c3 + f1.y;

    // Visibility: sigmoid
    float vt0 = 1.f / (1.f + __expf(-c4));
    float vt1 = 1.f - vt0;

    float tb = __ldg(t + b);
    float w0 = (1.f - tb) * vt0;
    float w1 = tb * vt1;
    float inv_den = 1.f / (w0 + w1 + 1e-12f);

    const float* img0 = I0 + (size_t)b * (HW * 3);
    const float* img1 = I1 + (size_t)b * (HW * 3);

    float gx = (float)xi, gy = (float)yi;
    float3 g0 = bilerp3(img0, gx + ft0x, gy + ft0y);
    float3 g1 = bilerp3(img1, gx + ft1x, gy + ft1y);

    float* o = out + (size_t)idx * 3;
    o[0] = (w0 * g0.x + w1 * g1.x) * inv_den;
    o[1] = (w0 * g0.y + w1 * g1.y) * inv_den;
    o[2] = (w0 * g0.z + w1 * g1.z) * inv_den;
}

extern "C" void kernel_launch(void* const* d_in, const int* in_sizes, int n_in,
                              void* d_out, int out_size) {
    const float* t      = (const float*)d_in[0];
    const float* I0     = (const float*)d_in[1];
    const float* I1     = (const float*)d_in[2];
    const float* interp = (const float*)d_in[3];
    const float* F0     = (const float*)d_in[4];
    const float* F1     = (const float*)d_in[5];
    float* out = (float*)d_out;

    int threads = 256;
    int blocks = (NPIX + threads - 1) / threads;
    imagecomp_kernel<<<blocks, threads>>>(t, I0, I1, interp, F0, F1, out);
}